// round 15
// baseline (speedup 1.0000x reference)
#include <cuda_runtime.h>
#include <cuda_bf16.h>
#include <math.h>
#include <stdint.h>
#include <string.h>

#define BQ 16
#define SEQ 1024
#define RDIM 1024
#define NHID 1024
#define HEADS 8
#define DKH 128

#define IN_N ((size_t)BQ * SEQ * RDIM)
#define W_N  ((size_t)NHID * RDIM)
#define O_N  ((size_t)BQ * SEQ * NHID)
#define ATT_NN ((size_t)BQ * HEADS * SEQ * SEQ)

// ======================= static scratch ==========================================
__device__ __nv_bfloat16 g_in3h[3 * IN_N], g_in3l[3 * IN_N];    // q,k,v inputs hi/lo
__device__ __nv_bfloat16 g_w4h[4 * W_N], g_w4l[4 * W_N];        // Wq,Wk,Wv,Wm transposed hi/lo
__device__ __nv_bfloat16 g_qkvh[3 * O_N], g_qkvl[3 * O_N];      // q,k,v projected hi/lo
__device__ __nv_bfloat16 g_vth[O_N], g_vtl[O_N];                // v transposed per batch
__device__ __nv_bfloat16 g_aedh[O_N], g_aedl[O_N];
__device__ __nv_bfloat16 g_atth[ATT_NN], g_attl[ATT_NN];        // softmax(att) hi/lo
__device__ float g_bias3[3 * NHID];
__device__ float g_attf[ATT_NN];                                // fallback if att not in d_out
__device__ unsigned char g_mask[(size_t)BQ * SEQ];
__device__ int g_mask_mode;

// ======================= small helpers ===========================================
__device__ __forceinline__ uint32_t s2u(const void* p) {
    uint32_t a;
    asm("{ .reg .u64 t; cvta.to.shared.u64 t, %1; cvt.u32.u64 %0, t; }" : "=r"(a) : "l"(p));
    return a;
}
__device__ __forceinline__ void f2hl(float x, __nv_bfloat16& h, __nv_bfloat16& l) {
    h = __float2bfloat16(x);
    l = __float2bfloat16(x - __bfloat162float(h));
}
__device__ __forceinline__ uint32_t pk2(__nv_bfloat16 a, __nv_bfloat16 b) {
    __nv_bfloat162 t; t.x = a; t.y = b;
    uint32_t u; memcpy(&u, &t, 4);
    return u;
}
__device__ __forceinline__ void cpa16(uint32_t s, const void* g) {
    asm volatile("cp.async.cg.shared.global [%0], [%1], 16;" :: "r"(s), "l"(g) : "memory");
}
__device__ __forceinline__ void ldm_x4(uint32_t r[4], uint32_t addr) {
    asm volatile("ldmatrix.sync.aligned.m8n8.x4.shared.b16 {%0,%1,%2,%3}, [%4];"
                 : "=r"(r[0]), "=r"(r[1]), "=r"(r[2]), "=r"(r[3]) : "r"(addr));
}
__device__ __forceinline__ void mma_bf16(float* c, const uint32_t* a, uint32_t b0, uint32_t b1) {
    asm volatile(
        "mma.sync.aligned.m16n8k16.row.col.f32.bf16.bf16.f32 "
        "{%0,%1,%2,%3}, {%4,%5,%6,%7}, {%8,%9}, {%0,%1,%2,%3};"
        : "+f"(c[0]), "+f"(c[1]), "+f"(c[2]), "+f"(c[3])
        : "r"(a[0]), "r"(a[1]), "r"(a[2]), "r"(a[3]), "r"(b0), "r"(b1));
}

// gemm3: 128x64 tile, 2 stages of 48KB -> 2 CTAs/SM
#define G3_STAGE 49152
#define GEMM_SMEM (2 * G3_STAGE)           // 98304

// ======================= mask canonicalization ===================================
__global__ void detect_mask_mode(const unsigned int* __restrict__ m) {
    __shared__ int s_non01f, s_f32w;
    if (threadIdx.x == 0) { s_non01f = 0; s_f32w = 0; }
    __syncthreads();
    int ln = 0, lf = 0;
    for (int i = threadIdx.x; i < 4096; i += blockDim.x) {
        unsigned int w = m[i];
        if (w == 0x3F800000u) lf = 1;
        else if (w > 1u) ln = 1;
    }
    if (ln) atomicOr(&s_non01f, 1);
    if (lf) atomicOr(&s_f32w, 1);
    __syncthreads();
    if (threadIdx.x == 0) {
        if (s_non01f) g_mask_mode = 0;
        else if (s_f32w) g_mask_mode = 2;
        else g_mask_mode = 1;
    }
}
__global__ void convert_mask(const void* __restrict__ m, unsigned char* __restrict__ outm, int n) {
    int i = blockIdx.x * blockDim.x + threadIdx.x;
    if (i >= n) return;
    int mode = g_mask_mode;
    unsigned char r;
    if (mode == 0)      r = ((const unsigned char*)m)[i] ? 1 : 0;
    else if (mode == 1) r = ((const int*)m)[i] ? 1 : 0;
    else                r = (((const float*)m)[i] != 0.0f) ? 1 : 0;
    outm[i] = r;
}

__global__ void gather_bias(const float* __restrict__ b0, const float* __restrict__ b1,
                            const float* __restrict__ b2, float* __restrict__ dst) {
    int i = threadIdx.x + blockIdx.x * blockDim.x;
    if (i < NHID) {
        dst[i] = b0[i];
        dst[NHID + i] = b1[i];
        dst[2 * NHID + i] = b2[i];
    }
}

// ======================= conversions (fused) =====================================
__global__ void conv_all(const float* __restrict__ q, const float* __restrict__ k,
                         const float* __restrict__ v,
                         __nv_bfloat16* __restrict__ hbase, __nv_bfloat16* __restrict__ lbase,
                         int n4) {
    int i = blockIdx.x * blockDim.x + threadIdx.x;
    if (i >= n4) return;
    int sel = blockIdx.y;
    const float* s = (sel == 0) ? q : (sel == 1) ? k : v;
    __nv_bfloat16* h = hbase + (size_t)sel * IN_N;
    __nv_bfloat16* l = lbase + (size_t)sel * IN_N;
    float4 vv = ((const float4*)s)[i];
    __nv_bfloat16 h0, l0, h1, l1, h2, l2, h3, l3;
    f2hl(vv.x, h0, l0); f2hl(vv.y, h1, l1); f2hl(vv.z, h2, l2); f2hl(vv.w, h3, l3);
    __nv_bfloat162 a, b, c, d;
    a.x = h0; a.y = h1; b.x = h2; b.y = h3;
    c.x = l0; c.y = l1; d.x = l2; d.y = l3;
    ((__nv_bfloat162*)h)[i * 2] = a;
    ((__nv_bfloat162*)h)[i * 2 + 1] = b;
    ((__nv_bfloat162*)l)[i * 2] = c;
    ((__nv_bfloat162*)l)[i * 2 + 1] = d;
}

// W [K,N] f32 -> Wt [N,K] hi/lo bf16, 4 weights fused (blockIdx.z selects slice)
__global__ void transW_all(const float* __restrict__ W0, const float* __restrict__ W1,
                           const float* __restrict__ W2, const float* __restrict__ W3,
                           __nv_bfloat16* __restrict__ hbase, __nv_bfloat16* __restrict__ lbase) {
    int s = blockIdx.z;
    const float* W = (s == 0) ? W0 : (s == 1) ? W1 : (s == 2) ? W2 : W3;
    __nv_bfloat16* th = hbase + (size_t)s * W_N;
    __nv_bfloat16* tl = lbase + (size_t)s * W_N;
    __shared__ float tile[32][33];
    int n = blockIdx.x * 32 + threadIdx.x;
    int k0 = blockIdx.y * 32;
    for (int i = threadIdx.y; i < 32; i += 8)
        tile[i][threadIdx.x] = W[(long long)(k0 + i) * NHID + n];
    __syncthreads();
    int k = k0 + threadIdx.x;
    int nr0 = blockIdx.x * 32;
    for (int i = threadIdx.y; i < 32; i += 8) {
        float f = tile[threadIdx.x][i];
        __nv_bfloat16 h, l;
        f2hl(f, h, l);
        th[(long long)(nr0 + i) * RDIM + k] = h;
        tl[(long long)(nr0 + i) * RDIM + k] = l;
    }
}

// v [b, t, c] bf16 -> vT [b, c, t]  (per-b 1024x1024 transpose, hi and lo)
__global__ void transV(const __nv_bfloat16* __restrict__ vh, const __nv_bfloat16* __restrict__ vl,
                       __nv_bfloat16* __restrict__ oh, __nv_bfloat16* __restrict__ ol) {
    int b = blockIdx.z;
    __shared__ __nv_bfloat16 th[32][33], tl2[32][33];
    long long base = (long long)b * SEQ * NHID;
    int c = blockIdx.x * 32 + threadIdx.x;
    int t0 = blockIdx.y * 32;
    for (int i = threadIdx.y; i < 32; i += 8) {
        th[i][threadIdx.x] = vh[base + (long long)(t0 + i) * NHID + c];
        tl2[i][threadIdx.x] = vl[base + (long long)(t0 + i) * NHID + c];
    }
    __syncthreads();
    int t = t0 + threadIdx.x;
    int c0 = blockIdx.x * 32;
    for (int i = threadIdx.y; i < 32; i += 8) {
        oh[base + (long long)(c0 + i) * SEQ + t] = th[threadIdx.x][i];
        ol[base + (long long)(c0 + i) * SEQ + t] = tl2[threadIdx.x][i];
    }
}

// ======================= shared GEMM building blocks =============================
__device__ __forceinline__ void load_mat(uint32_t sBase, const __nv_bfloat16* g, int ld, int kt, int tid) {
#pragma unroll
    for (int i = 0; i < 4; i++) {
        int u = tid + (i << 8);
        int r = u >> 3, cu = u & 7;
        uint32_t off = (uint32_t)(r * 128 + cu * 16);
        off ^= (off >> 3) & 0x70;
        cpa16(sBase + off, g + (long long)r * ld + kt + (cu << 3));
    }
}
__device__ __forceinline__ void load_mat64(uint32_t sBase, const __nv_bfloat16* g, int ld, int kt, int tid) {
#pragma unroll
    for (int i = 0; i < 2; i++) {
        int u = tid + (i << 8);
        int r = u >> 3, cu = u & 7;
        uint32_t off = (uint32_t)(r * 128 + cu * 16);
        off ^= (off >> 3) & 0x70;
        cpa16(sBase + off, g + (long long)r * ld + kt + (cu << 3));
    }
}

__device__ __forceinline__ uint32_t swadr(uint32_t base, int row, int bcol) {
    return base + (uint32_t)(row * 128) + (uint32_t)(bcol ^ ((row & 7) << 4));
}

// ======================= HMMA bf16x3 GEMM (128x64 tile, 2 CTAs/SM) ===============
// C[M,N] = sum_k A[M,K] * Bt[N,K]. 8 warps, warp tile 32x32.
// EPI: 0 = hi/lo bf16 out (+opt bias), 1 = f32 out (+bias), 2 = scores (scale+mask f32)
__device__ __forceinline__ void g3_load_chunk(uint32_t stage,
                                              const __nv_bfloat16* Azh, const __nv_bfloat16* Azl, int lda,
                                              const __nv_bfloat16* Bzh, const __nv_bfloat16* Bzl, int ldb,
                                              int kt, int tid) {
    load_mat(stage,           Azh, lda, kt, tid);
    load_mat(stage + 16384,   Azl, lda, kt, tid);
    load_mat64(stage + 32768, Bzh, ldb, kt, tid);
    load_mat64(stage + 40960, Bzl, ldb, kt, tid);
    asm volatile("cp.async.commit_group;" ::: "memory");
}

template <int EPI>
__global__ void __launch_bounds__(256, 2) gemm3(
    const __nv_bfloat16* __restrict__ Ah, const __nv_bfloat16* __restrict__ Al,
    int lda, long long sA1, long long sA2,
    const __nv_bfloat16* __restrict__ Bh, const __nv_bfloat16* __restrict__ Bl,
    int ldb, long long sB1, long long sB2,
    const float* __restrict__ bias, long long sBias,
    float* __restrict__ Cf, __nv_bfloat16* __restrict__ Ch, __nv_bfloat16* __restrict__ Cl,
    int ldc, long long sC1, long long sC2,
    int Ktot, const unsigned char* __restrict__ mask, float scale)
{
    extern __shared__ char smem[];
    uint32_t sb = s2u(smem);
    int tid = threadIdx.x;
    int wid = tid >> 5, lane = tid & 31;
    int wm = wid & 3, wn = wid >> 2;

    int z = blockIdx.z;
    int zb = z / HEADS, zh = z % HEADS;
    int m0 = blockIdx.y * 128, n0 = blockIdx.x * 64;
    const __nv_bfloat16* Azh = Ah + zb * sA1 + zh * sA2 + (long long)m0 * lda;
    const __nv_bfloat16* Azl = Al + zb * sA1 + zh * sA2 + (long long)m0 * lda;
    const __nv_bfloat16* Bzh = Bh + zb * sB1 + zh * sB2 + (long long)n0 * ldb;
    const __nv_bfloat16* Bzl = Bl + zb * sB1 + zh * sB2 + (long long)n0 * ldb;
    const float* biasz = bias ? (bias + zh * sBias) : nullptr;

    float acc[2][4][4];
#pragma unroll
    for (int i = 0; i < 2; i++)
#pragma unroll
        for (int j = 0; j < 4; j++)
#pragma unroll
            for (int q = 0; q < 4; q++) acc[i][j][q] = 0.f;

    int nch = Ktot >> 6;

    g3_load_chunk(sb, Azh, Azl, lda, Bzh, Bzl, ldb, 0, tid);
    if (nch > 1)
        g3_load_chunk(sb + G3_STAGE, Azh, Azl, lda, Bzh, Bzl, ldb, 64, tid);

    int aRow = (lane & 15);
    int aColB = (lane >> 4) << 4;
    int bRow = (lane & 7) + ((lane >> 4) << 3);
    int bColB = ((lane >> 3) & 1) << 4;

    for (int c = 0; c < nch; c++) {
        if (c < nch - 1) {
            asm volatile("cp.async.wait_group 1;" ::: "memory");
        } else {
            asm volatile("cp.async.wait_group 0;" ::: "memory");
        }
        __syncthreads();

        uint32_t bp = sb + (uint32_t)(c & 1) * G3_STAGE;
        uint32_t aBh = bp, aBl = bp + 16384, bBh = bp + 32768, bBl = bp + 40960;

#pragma unroll
        for (int ks = 0; ks < 4; ks++) {
            int kb = ks << 5;
            uint32_t ah[2][4], al[2][4], bh[2][4], bl[2][4];
#pragma unroll
            for (int mi = 0; mi < 2; mi++) {
                int r = wm * 32 + mi * 16 + aRow;
                ldm_x4(ah[mi], swadr(aBh, r, kb + aColB));
                ldm_x4(al[mi], swadr(aBl, r, kb + aColB));
            }
#pragma unroll
            for (int j = 0; j < 2; j++) {
                int rn = wn * 32 + j * 16 + bRow;
                ldm_x4(bh[j], swadr(bBh, rn, kb + bColB));
                ldm_x4(bl[j], swadr(bBl, rn, kb + bColB));
            }
            // hh
#pragma unroll
            for (int mi = 0; mi < 2; mi++)
#pragma unroll
                for (int j = 0; j < 2; j++)
#pragma unroll
                    for (int nn = 0; nn < 2; nn++)
                        mma_bf16(acc[mi][2 * j + nn], ah[mi], bh[j][nn * 2], bh[j][nn * 2 + 1]);
            // hl
#pragma unroll
            for (int mi = 0; mi < 2; mi++)
#pragma unroll
                for (int j = 0; j < 2; j++)
#pragma unroll
                    for (int nn = 0; nn < 2; nn++)
                        mma_bf16(acc[mi][2 * j + nn], ah[mi], bl[j][nn * 2], bl[j][nn * 2 + 1]);
            // lh
#pragma unroll
            for (int mi = 0; mi < 2; mi++)
#pragma unroll
                for (int j = 0; j < 2; j++)
#pragma unroll
                    for (int nn = 0; nn < 2; nn++)
                        mma_bf16(acc[mi][2 * j + nn], al[mi], bh[j][nn * 2], bh[j][nn * 2 + 1]);
        }
        __syncthreads();

        if (c + 2 < nch)
            g3_load_chunk(sb + (uint32_t)(c & 1) * G3_STAGE,
                          Azh, Azl, lda, Bzh, Bzl, ldb, (c + 2) << 6, tid);
    }

    // ---------------- epilogue -----------------
    int gm = m0 + wm * 32;
    int gn = n0 + wn * 32;
    long long cbase = zb * sC1 + zh * sC2;

#pragma unroll
    for (int mi = 0; mi < 2; mi++) {
#pragma unroll
        for (int half = 0; half < 2; half++) {
            int r = gm + mi * 16 + half * 8 + (lane >> 2);
#pragma unroll
            for (int ni = 0; ni < 4; ni++) {
                int cc = gn + ni * 8 + (lane & 3) * 2;
                float f0 = acc[mi][ni][half * 2 + 0];
                float f1 = acc[mi][ni][half * 2 + 1];
                if (EPI == 0) {
                    if (biasz) { f0 += biasz[cc]; f1 += biasz[cc + 1]; }
                    __nv_bfloat16 h0, l0, h1, l1;
                    f2hl(f0, h0, l0); f2hl(f1, h1, l1);
                    __nv_bfloat162 vh2, vl2;
                    vh2.x = h0; vh2.y = h1; vl2.x = l0; vl2.y = l1;
                    *(__nv_bfloat162*)(Ch + cbase + (long long)r * ldc + cc) = vh2;
                    *(__nv_bfloat162*)(Cl + cbase + (long long)r * ldc + cc) = vl2;
                } else if (EPI == 1) {
                    float2 v;
                    v.x = f0 + biasz[cc];
                    v.y = f1 + biasz[cc + 1];
                    *(float2*)(Cf + cbase + (long long)r * ldc + cc) = v;
                } else {
                    const unsigned char* mb = mask + (long long)zb * SEQ;
                    float2 v;
                    v.x = mb[cc]     ? -1e9f : f0 * scale;
                    v.y = mb[cc + 1] ? -1e9f : f1 * scale;
                    *(float2*)(Cf + cbase + (long long)r * ldc + cc) = v;
                }
            }
        }
    }
}

// ======================= softmax (f32 in place + hi/lo bf16 out) =================
__global__ __launch_bounds__(128) void softmax_rows(float* __restrict__ att,
                                                    __nv_bfloat16* __restrict__ ah,
                                                    __nv_bfloat16* __restrict__ al)
{
    long long rowi = blockIdx.x;
    float* p = att + rowi * SEQ;
    int t = threadIdx.x;
    int w = t >> 5, l = t & 31;
    __shared__ float smx[4], ssm[4];

    // vectorized: thread t owns elements [t*8, t*8+8)
    float4 va = ((const float4*)p)[t * 2];
    float4 vb = ((const float4*)p)[t * 2 + 1];
    float v[8] = {va.x, va.y, va.z, va.w, vb.x, vb.y, vb.z, vb.w};

    float mx = v[0];
#pragma unroll
    for (int i = 1; i < 8; i++) mx = fmaxf(mx, v[i]);
#pragma unroll
    for (int o = 16; o; o >>= 1) mx = fmaxf(mx, __shfl_xor_sync(0xffffffffu, mx, o));
    if (l == 0) smx[w] = mx;
    __syncthreads();
    mx = fmaxf(fmaxf(smx[0], smx[1]), fmaxf(smx[2], smx[3]));

    float s = 0.f;
#pragma unroll
    for (int i = 0; i < 8; i++) {
        v[i] = __expf(v[i] - mx);
        s += v[i];
    }
#pragma unroll
    for (int o = 16; o; o >>= 1) s += __shfl_xor_sync(0xffffffffu, s, o);
    if (l == 0) ssm[w] = s;
    __syncthreads();
    s = ssm[0] + ssm[1] + ssm[2] + ssm[3];
    float inv = 1.f / s;

#pragma unroll
    for (int i = 0; i < 8; i++) v[i] *= inv;
    float4 o0 = make_float4(v[0], v[1], v[2], v[3]);
    float4 o1 = make_float4(v[4], v[5], v[6], v[7]);
    ((float4*)p)[t * 2] = o0;
    ((float4*)p)[t * 2 + 1] = o1;

    __nv_bfloat16 hh[8], ll[8];
#pragma unroll
    for (int i = 0; i < 8; i++) f2hl(v[i], hh[i], ll[i]);
    uint4 uh, ul;
    uh.x = pk2(hh[0], hh[1]); uh.y = pk2(hh[2], hh[3]);
    uh.z = pk2(hh[4], hh[5]); uh.w = pk2(hh[6], hh[7]);
    ul.x = pk2(ll[0], ll[1]); ul.y = pk2(ll[2], ll[3]);
    ul.z = pk2(ll[4], ll[5]); ul.w = pk2(ll[6], ll[7]);
    ((uint4*)(ah + rowi * SEQ))[t] = uh;
    ((uint4*)(al + rowi * SEQ))[t] = ul;
}

// ======================= host ====================================================
extern "C" void kernel_launch(void* const* d_in, const int* in_sizes, int n_in,
                              void* d_out, int out_size)
{
    const float* v_in  = (const float*)d_in[0];
    const float* key   = (const float*)d_in[1];
    const float* query = (const float*)d_in[2];
    const void*  mask  = d_in[3];
    const float* Wq = (const float*)d_in[4];
    const float* bq = (const float*)d_in[5];
    const float* Wk = (const float*)d_in[6];
    const float* bk = (const float*)d_in[7];
    const float* Wv = (const float*)d_in[8];
    const float* bv = (const float*)d_in[9];
    const float* Wm = (const float*)d_in[10];
    const float* bm = (const float*)d_in[11];
    float* out = (float*)d_out;

    const long long ATTED_N = (long long)BQ * SEQ * NHID;
    const long long ATT_N   = (long long)BQ * HEADS * SEQ * SEQ;

#define GETP(sym, ty, var) ty* var; cudaGetSymbolAddress((void**)&var, sym)
    GETP(g_in3h, __nv_bfloat16, in3h); GETP(g_in3l, __nv_bfloat16, in3l);
    GETP(g_w4h, __nv_bfloat16, w4h); GETP(g_w4l, __nv_bfloat16, w4l);
    GETP(g_qkvh, __nv_bfloat16, qkvh); GETP(g_qkvl, __nv_bfloat16, qkvl);
    GETP(g_vth, __nv_bfloat16, vth); GETP(g_vtl, __nv_bfloat16, vtl);
    GETP(g_aedh, __nv_bfloat16, aedh); GETP(g_aedl, __nv_bfloat16, aedl);
    GETP(g_atth, __nv_bfloat16, atth); GETP(g_attl, __nv_bfloat16, attl);
    GETP(g_bias3, float, bias3);
    GETP(g_attf, float, attf);
    GETP(g_mask, unsigned char, maskp);
#undef GETP

    __nv_bfloat16* qh = qkvh;               __nv_bfloat16* ql = qkvl;
    __nv_bfloat16* kh = qkvh + O_N;         __nv_bfloat16* kl = qkvl + O_N;
    __nv_bfloat16* vh = qkvh + 2 * O_N;     __nv_bfloat16* vl = qkvl + 2 * O_N;

    float* att_ptr;
    float* atted_ptr = out;
    if ((long long)out_size >= ATTED_N + ATT_N) {
        att_ptr = out + ATTED_N;
    } else {
        att_ptr = attf;
    }

    cudaFuncSetAttribute(gemm3<0>, cudaFuncAttributeMaxDynamicSharedMemorySize, GEMM_SMEM);
    cudaFuncSetAttribute(gemm3<1>, cudaFuncAttributeMaxDynamicSharedMemorySize, GEMM_SMEM);
    cudaFuncSetAttribute(gemm3<2>, cudaFuncAttributeMaxDynamicSharedMemorySize, GEMM_SMEM);

    const float scale = 1.0f / sqrtf((float)DKH);
    dim3 blk(256);

    // (0) input conversions (fused q/k/v into contiguous block)
    {
        int n4 = (int)(IN_N / 4);
        dim3 g((n4 + 255) / 256, 3);
        conv_all<<<g, 256>>>(query, key, v_in, in3h, in3l, n4);
    }
    // (1) weight transposes (fused, contiguous)
    {
        dim3 g(32, 32, 4), b(32, 8);
        transW_all<<<g, b>>>(Wq, Wk, Wv, Wm, w4h, w4l);
    }
    // (2) bias gather
    gather_bias<<<(NHID + 255) / 256, 256>>>(bq, bk, bv, bias3);

    // (3) ALL THREE projections in ONE launch: z in {0,1,2} selects q/k/v
    {
        dim3 grid(NHID / 64, (BQ * SEQ) / 128, 3);
        gemm3<0><<<grid, blk, GEMM_SMEM>>>(in3h, in3l, RDIM, 0, (long long)IN_N,
                                           w4h, w4l, RDIM, 0, (long long)W_N,
                                           bias3, (long long)NHID,
                                           nullptr, qkvh, qkvl, NHID, 0, (long long)O_N,
                                           RDIM, nullptr, 0.f);
    }

    // (4) V transpose per batch
    {
        dim3 g(32, 32, BQ), b(32, 8);
        transV<<<g, b>>>(vh, vl, vth, vtl);
    }

    // (5,6) mask canonicalization
    detect_mask_mode<<<1, 256>>>((const unsigned int*)mask);
    convert_mask<<<(BQ * SEQ + 255) / 256, 256>>>(mask, maskp, BQ * SEQ);

    // (7) Scores: per (b,h): M=N=1024, K=128 -> f32 att with scale+mask
    {
        dim3 grid(SEQ / 64, SEQ / 128, BQ * HEADS);
        gemm3<2><<<grid, blk, GEMM_SMEM>>>(qh, ql, NHID, (long long)SEQ * NHID, (long long)DKH,
                                           kh, kl, NHID, (long long)SEQ * NHID, (long long)DKH,
                                           nullptr, 0,
                                           att_ptr, nullptr, nullptr, SEQ,
                                           (long long)HEADS * SEQ * SEQ, (long long)SEQ * SEQ,
                                           DKH, maskp, scale);
    }

    // (8) Softmax in place (f32) + hi/lo bf16 copies for PV
    softmax_rows<<<(unsigned)(BQ * HEADS * SEQ), dim3(128)>>>(att_ptr, atth, attl);

    // (9) PV as pure 2-CTA gemm3: atted = att @ V^T -> hi/lo bf16
    {
        dim3 grid(DKH / 64, SEQ / 128, BQ * HEADS);
        gemm3<0><<<grid, blk, GEMM_SMEM>>>(atth, attl, SEQ,
                                           (long long)HEADS * SEQ * SEQ, (long long)SEQ * SEQ,
                                           vth, vtl, SEQ,
                                           (long long)SEQ * NHID, (long long)DKH * SEQ,
                                           nullptr, 0,
                                           nullptr, aedh, aedl, NHID,
                                           (long long)SEQ * NHID, (long long)DKH,
                                           SEQ, nullptr, 0.f);
    }

    // (10) Output projection (weight slice 3 = Wm)
    {
        dim3 grid(NHID / 64, (BQ * SEQ) / 128, 1);
        gemm3<1><<<grid, blk, GEMM_SMEM>>>(aedh, aedl, NHID, 0, 0,
                                           w4h + 3 * W_N, w4l + 3 * W_N, NHID, 0, 0,
                                           bm, 0,
                                           atted_ptr, nullptr, nullptr, NHID, 0, 0,
                                           NHID, nullptr, 0.f);
    }
}

// round 16
// speedup vs baseline: 1.0127x; 1.0127x over previous
#include <cuda_runtime.h>
#include <cuda_bf16.h>
#include <math.h>
#include <stdint.h>
#include <string.h>

#define BQ 16
#define SEQ 1024
#define RDIM 1024
#define NHID 1024
#define HEADS 8
#define DKH 128

#define IN_N ((size_t)BQ * SEQ * RDIM)
#define W_N  ((size_t)NHID * RDIM)
#define O_N  ((size_t)BQ * SEQ * NHID)
#define ATT_NN ((size_t)BQ * HEADS * SEQ * SEQ)

// ======================= static scratch ==========================================
__device__ __nv_bfloat16 g_in3h[3 * IN_N], g_in3l[3 * IN_N];
__device__ __nv_bfloat16 g_w4h[4 * W_N], g_w4l[4 * W_N];
__device__ __nv_bfloat16 g_qkvh[3 * O_N], g_qkvl[3 * O_N];
__device__ __nv_bfloat16 g_vth[O_N], g_vtl[O_N];
__device__ __nv_bfloat16 g_aedh[O_N], g_aedl[O_N];
__device__ __nv_bfloat16 g_atth[ATT_NN], g_attl[ATT_NN];
__device__ float g_bias3[3 * NHID];
__device__ float g_attf[ATT_NN];
__device__ unsigned char g_mask[(size_t)BQ * SEQ];
__device__ int g_mask_mode;

// ======================= small helpers ===========================================
__device__ __forceinline__ uint32_t s2u(const void* p) {
    uint32_t a;
    asm("{ .reg .u64 t; cvta.to.shared.u64 t, %1; cvt.u32.u64 %0, t; }" : "=r"(a) : "l"(p));
    return a;
}
__device__ __forceinline__ void f2hl(float x, __nv_bfloat16& h, __nv_bfloat16& l) {
    h = __float2bfloat16(x);
    l = __float2bfloat16(x - __bfloat162float(h));
}
__device__ __forceinline__ uint32_t pk2(__nv_bfloat16 a, __nv_bfloat16 b) {
    __nv_bfloat162 t; t.x = a; t.y = b;
    uint32_t u; memcpy(&u, &t, 4);
    return u;
}
__device__ __forceinline__ void cpa16(uint32_t s, const void* g) {
    asm volatile("cp.async.cg.shared.global [%0], [%1], 16;" :: "r"(s), "l"(g) : "memory");
}
__device__ __forceinline__ void ldm_x4(uint32_t r[4], uint32_t addr) {
    asm volatile("ldmatrix.sync.aligned.m8n8.x4.shared.b16 {%0,%1,%2,%3}, [%4];"
                 : "=r"(r[0]), "=r"(r[1]), "=r"(r[2]), "=r"(r[3]) : "r"(addr));
}
__device__ __forceinline__ void mma_bf16(float* c, const uint32_t* a, uint32_t b0, uint32_t b1) {
    asm volatile(
        "mma.sync.aligned.m16n8k16.row.col.f32.bf16.bf16.f32 "
        "{%0,%1,%2,%3}, {%4,%5,%6,%7}, {%8,%9}, {%0,%1,%2,%3};"
        : "+f"(c[0]), "+f"(c[1]), "+f"(c[2]), "+f"(c[3])
        : "r"(a[0]), "r"(a[1]), "r"(a[2]), "r"(a[3]), "r"(b0), "r"(b1));
}

// gemm3: 128x64 tile, 128 threads (4 warps, warp tile 32x64), 2 stages of 48KB -> 2 CTAs/SM
#define G3_STAGE 49152
#define GEMM_SMEM (2 * G3_STAGE)           // 98304

// ======================= mask canonicalization ===================================
__global__ void detect_mask_mode(const unsigned int* __restrict__ m) {
    __shared__ int s_non01f, s_f32w;
    if (threadIdx.x == 0) { s_non01f = 0; s_f32w = 0; }
    __syncthreads();
    int ln = 0, lf = 0;
    for (int i = threadIdx.x; i < 4096; i += blockDim.x) {
        unsigned int w = m[i];
        if (w == 0x3F800000u) lf = 1;
        else if (w > 1u) ln = 1;
    }
    if (ln) atomicOr(&s_non01f, 1);
    if (lf) atomicOr(&s_f32w, 1);
    __syncthreads();
    if (threadIdx.x == 0) {
        if (s_non01f) g_mask_mode = 0;
        else if (s_f32w) g_mask_mode = 2;
        else g_mask_mode = 1;
    }
}
__global__ void convert_mask(const void* __restrict__ m, unsigned char* __restrict__ outm, int n) {
    int i = blockIdx.x * blockDim.x + threadIdx.x;
    if (i >= n) return;
    int mode = g_mask_mode;
    unsigned char r;
    if (mode == 0)      r = ((const unsigned char*)m)[i] ? 1 : 0;
    else if (mode == 1) r = ((const int*)m)[i] ? 1 : 0;
    else                r = (((const float*)m)[i] != 0.0f) ? 1 : 0;
    outm[i] = r;
}

__global__ void gather_bias(const float* __restrict__ b0, const float* __restrict__ b1,
                            const float* __restrict__ b2, float* __restrict__ dst) {
    int i = threadIdx.x + blockIdx.x * blockDim.x;
    if (i < NHID) {
        dst[i] = b0[i];
        dst[NHID + i] = b1[i];
        dst[2 * NHID + i] = b2[i];
    }
}

// ======================= conversions (fused) =====================================
__global__ void conv_all(const float* __restrict__ q, const float* __restrict__ k,
                         const float* __restrict__ v,
                         __nv_bfloat16* __restrict__ hbase, __nv_bfloat16* __restrict__ lbase,
                         int n4) {
    int i = blockIdx.x * blockDim.x + threadIdx.x;
    if (i >= n4) return;
    int sel = blockIdx.y;
    const float* s = (sel == 0) ? q : (sel == 1) ? k : v;
    __nv_bfloat16* h = hbase + (size_t)sel * IN_N;
    __nv_bfloat16* l = lbase + (size_t)sel * IN_N;
    float4 vv = ((const float4*)s)[i];
    __nv_bfloat16 h0, l0, h1, l1, h2, l2, h3, l3;
    f2hl(vv.x, h0, l0); f2hl(vv.y, h1, l1); f2hl(vv.z, h2, l2); f2hl(vv.w, h3, l3);
    __nv_bfloat162 a, b, c, d;
    a.x = h0; a.y = h1; b.x = h2; b.y = h3;
    c.x = l0; c.y = l1; d.x = l2; d.y = l3;
    ((__nv_bfloat162*)h)[i * 2] = a;
    ((__nv_bfloat162*)h)[i * 2 + 1] = b;
    ((__nv_bfloat162*)l)[i * 2] = c;
    ((__nv_bfloat162*)l)[i * 2 + 1] = d;
}

// W [K,N] f32 -> Wt [N,K] hi/lo bf16, 4 weights fused
__global__ void transW_all(const float* __restrict__ W0, const float* __restrict__ W1,
                           const float* __restrict__ W2, const float* __restrict__ W3,
                           __nv_bfloat16* __restrict__ hbase, __nv_bfloat16* __restrict__ lbase) {
    int s = blockIdx.z;
    const float* W = (s == 0) ? W0 : (s == 1) ? W1 : (s == 2) ? W2 : W3;
    __nv_bfloat16* th = hbase + (size_t)s * W_N;
    __nv_bfloat16* tl = lbase + (size_t)s * W_N;
    __shared__ float tile[32][33];
    int n = blockIdx.x * 32 + threadIdx.x;
    int k0 = blockIdx.y * 32;
    for (int i = threadIdx.y; i < 32; i += 8)
        tile[i][threadIdx.x] = W[(long long)(k0 + i) * NHID + n];
    __syncthreads();
    int k = k0 + threadIdx.x;
    int nr0 = blockIdx.x * 32;
    for (int i = threadIdx.y; i < 32; i += 8) {
        float f = tile[threadIdx.x][i];
        __nv_bfloat16 h, l;
        f2hl(f, h, l);
        th[(long long)(nr0 + i) * RDIM + k] = h;
        tl[(long long)(nr0 + i) * RDIM + k] = l;
    }
}

// v [b, t, c] bf16 -> vT [b, c, t]
__global__ void transV(const __nv_bfloat16* __restrict__ vh, const __nv_bfloat16* __restrict__ vl,
                       __nv_bfloat16* __restrict__ oh, __nv_bfloat16* __restrict__ ol) {
    int b = blockIdx.z;
    __shared__ __nv_bfloat16 th[32][33], tl2[32][33];
    long long base = (long long)b * SEQ * NHID;
    int c = blockIdx.x * 32 + threadIdx.x;
    int t0 = blockIdx.y * 32;
    for (int i = threadIdx.y; i < 32; i += 8) {
        th[i][threadIdx.x] = vh[base + (long long)(t0 + i) * NHID + c];
        tl2[i][threadIdx.x] = vl[base + (long long)(t0 + i) * NHID + c];
    }
    __syncthreads();
    int t = t0 + threadIdx.x;
    int c0 = blockIdx.x * 32;
    for (int i = threadIdx.y; i < 32; i += 8) {
        oh[base + (long long)(c0 + i) * SEQ + t] = th[threadIdx.x][i];
        ol[base + (long long)(c0 + i) * SEQ + t] = tl2[threadIdx.x][i];
    }
}

// ======================= shared GEMM building blocks (128 threads) ===============
__device__ __forceinline__ void load_mat(uint32_t sBase, const __nv_bfloat16* g, int ld, int kt, int tid) {
#pragma unroll
    for (int i = 0; i < 8; i++) {
        int u = tid + (i << 7);
        int r = u >> 3, cu = u & 7;
        uint32_t off = (uint32_t)(r * 128 + cu * 16);
        off ^= (off >> 3) & 0x70;
        cpa16(sBase + off, g + (long long)r * ld + kt + (cu << 3));
    }
}
__device__ __forceinline__ void load_mat64(uint32_t sBase, const __nv_bfloat16* g, int ld, int kt, int tid) {
#pragma unroll
    for (int i = 0; i < 4; i++) {
        int u = tid + (i << 7);
        int r = u >> 3, cu = u & 7;
        uint32_t off = (uint32_t)(r * 128 + cu * 16);
        off ^= (off >> 3) & 0x70;
        cpa16(sBase + off, g + (long long)r * ld + kt + (cu << 3));
    }
}

__device__ __forceinline__ uint32_t swadr(uint32_t base, int row, int bcol) {
    return base + (uint32_t)(row * 128) + (uint32_t)(bcol ^ ((row & 7) << 4));
}

// ======================= HMMA bf16x3 GEMM (128x64 tile, 4 warps, 2 CTAs/SM) ======
// C[M,N] = sum_k A[M,K] * Bt[N,K]. Warp tile 32x64 (wm = wid, full N width).
// EPI: 0 = hi/lo bf16 out (+opt bias), 1 = f32 out (+bias), 2 = scores (scale+mask f32)
__device__ __forceinline__ void g3_load_chunk(uint32_t stage,
                                              const __nv_bfloat16* Azh, const __nv_bfloat16* Azl, int lda,
                                              const __nv_bfloat16* Bzh, const __nv_bfloat16* Bzl, int ldb,
                                              int kt, int tid) {
    load_mat(stage,           Azh, lda, kt, tid);
    load_mat(stage + 16384,   Azl, lda, kt, tid);
    load_mat64(stage + 32768, Bzh, ldb, kt, tid);
    load_mat64(stage + 40960, Bzl, ldb, kt, tid);
    asm volatile("cp.async.commit_group;" ::: "memory");
}

template <int EPI>
__global__ void __launch_bounds__(128, 2) gemm3(
    const __nv_bfloat16* __restrict__ Ah, const __nv_bfloat16* __restrict__ Al,
    int lda, long long sA1, long long sA2,
    const __nv_bfloat16* __restrict__ Bh, const __nv_bfloat16* __restrict__ Bl,
    int ldb, long long sB1, long long sB2,
    const float* __restrict__ bias, long long sBias,
    float* __restrict__ Cf, __nv_bfloat16* __restrict__ Ch, __nv_bfloat16* __restrict__ Cl,
    int ldc, long long sC1, long long sC2,
    int Ktot, const unsigned char* __restrict__ mask, float scale)
{
    extern __shared__ char smem[];
    uint32_t sb = s2u(smem);
    int tid = threadIdx.x;
    int wid = tid >> 5, lane = tid & 31;
    int wm = wid;                       // warp rows: wm*32 .. wm*32+31; full 64 cols

    int z = blockIdx.z;
    int zb = z / HEADS, zh = z % HEADS;
    int m0 = blockIdx.y * 128, n0 = blockIdx.x * 64;
    const __nv_bfloat16* Azh = Ah + zb * sA1 + zh * sA2 + (long long)m0 * lda;
    const __nv_bfloat16* Azl = Al + zb * sA1 + zh * sA2 + (long long)m0 * lda;
    const __nv_bfloat16* Bzh = Bh + zb * sB1 + zh * sB2 + (long long)n0 * ldb;
    const __nv_bfloat16* Bzl = Bl + zb * sB1 + zh * sB2 + (long long)n0 * ldb;
    const float* biasz = bias ? (bias + zh * sBias) : nullptr;

    float acc[2][8][4];
#pragma unroll
    for (int i = 0; i < 2; i++)
#pragma unroll
        for (int j = 0; j < 8; j++)
#pragma unroll
            for (int q = 0; q < 4; q++) acc[i][j][q] = 0.f;

    int nch = Ktot >> 6;

    g3_load_chunk(sb, Azh, Azl, lda, Bzh, Bzl, ldb, 0, tid);
    if (nch > 1)
        g3_load_chunk(sb + G3_STAGE, Azh, Azl, lda, Bzh, Bzl, ldb, 64, tid);

    int aRow = (lane & 15);
    int aColB = (lane >> 4) << 4;
    int bRow = (lane & 7) + ((lane >> 4) << 3);
    int bColB = ((lane >> 3) & 1) << 4;

    for (int c = 0; c < nch; c++) {
        if (c < nch - 1) {
            asm volatile("cp.async.wait_group 1;" ::: "memory");
        } else {
            asm volatile("cp.async.wait_group 0;" ::: "memory");
        }
        __syncthreads();

        uint32_t bp = sb + (uint32_t)(c & 1) * G3_STAGE;
        uint32_t aBh = bp, aBl = bp + 16384, bBh = bp + 32768, bBl = bp + 40960;

#pragma unroll
        for (int ks = 0; ks < 4; ks++) {
            int kb = ks << 5;
            uint32_t ah[2][4], al[2][4], bh[4][4], bl[4][4];
#pragma unroll
            for (int mi = 0; mi < 2; mi++) {
                int r = wm * 32 + mi * 16 + aRow;
                ldm_x4(ah[mi], swadr(aBh, r, kb + aColB));
                ldm_x4(al[mi], swadr(aBl, r, kb + aColB));
            }
#pragma unroll
            for (int j = 0; j < 4; j++) {
                int rn = j * 16 + bRow;
                ldm_x4(bh[j], swadr(bBh, rn, kb + bColB));
                ldm_x4(bl[j], swadr(bBl, rn, kb + bColB));
            }
            // hh
#pragma unroll
            for (int mi = 0; mi < 2; mi++)
#pragma unroll
                for (int j = 0; j < 4; j++)
#pragma unroll
                    for (int nn = 0; nn < 2; nn++)
                        mma_bf16(acc[mi][2 * j + nn], ah[mi], bh[j][nn * 2], bh[j][nn * 2 + 1]);
            // hl
#pragma unroll
            for (int mi = 0; mi < 2; mi++)
#pragma unroll
                for (int j = 0; j < 4; j++)
#pragma unroll
                    for (int nn = 0; nn < 2; nn++)
                        mma_bf16(acc[mi][2 * j + nn], ah[mi], bl[j][nn * 2], bl[j][nn * 2 + 1]);
            // lh
#pragma unroll
            for (int mi = 0; mi < 2; mi++)
#pragma unroll
                for (int j = 0; j < 4; j++)
#pragma unroll
                    for (int nn = 0; nn < 2; nn++)
                        mma_bf16(acc[mi][2 * j + nn], al[mi], bh[j][nn * 2], bh[j][nn * 2 + 1]);
        }
        __syncthreads();

        if (c + 2 < nch)
            g3_load_chunk(sb + (uint32_t)(c & 1) * G3_STAGE,
                          Azh, Azl, lda, Bzh, Bzl, ldb, (c + 2) << 6, tid);
    }

    // ---------------- epilogue -----------------
    int gm = m0 + wm * 32;
    int gn = n0;
    long long cbase = zb * sC1 + zh * sC2;

#pragma unroll
    for (int mi = 0; mi < 2; mi++) {
#pragma unroll
        for (int half = 0; half < 2; half++) {
            int r = gm + mi * 16 + half * 8 + (lane >> 2);
#pragma unroll
            for (int ni = 0; ni < 8; ni++) {
                int cc = gn + ni * 8 + (lane & 3) * 2;
                float f0 = acc[mi][ni][half * 2 + 0];
                float f1 = acc[mi][ni][half * 2 + 1];
                if (EPI == 0) {
                    if (biasz) { f0 += biasz[cc]; f1 += biasz[cc + 1]; }
                    __nv_bfloat16 h0, l0, h1, l1;
                    f2hl(f0, h0, l0); f2hl(f1, h1, l1);
                    __nv_bfloat162 vh2, vl2;
                    vh2.x = h0; vh2.y = h1; vl2.x = l0; vl2.y = l1;
                    *(__nv_bfloat162*)(Ch + cbase + (long long)r * ldc + cc) = vh2;
                    *(__nv_bfloat162*)(Cl + cbase + (long long)r * ldc + cc) = vl2;
                } else if (EPI == 1) {
                    float2 v;
                    v.x = f0 + biasz[cc];
                    v.y = f1 + biasz[cc + 1];
                    *(float2*)(Cf + cbase + (long long)r * ldc + cc) = v;
                } else {
                    const unsigned char* mb = mask + (long long)zb * SEQ;
                    float2 v;
                    v.x = mb[cc]     ? -1e9f : f0 * scale;
                    v.y = mb[cc + 1] ? -1e9f : f1 * scale;
                    *(float2*)(Cf + cbase + (long long)r * ldc + cc) = v;
                }
            }
        }
    }
}

// ======================= softmax (f32 in place + hi/lo bf16 out) =================
__global__ __launch_bounds__(128) void softmax_rows(float* __restrict__ att,
                                                    __nv_bfloat16* __restrict__ ah,
                                                    __nv_bfloat16* __restrict__ al)
{
    long long rowi = blockIdx.x;
    float* p = att + rowi * SEQ;
    int t = threadIdx.x;
    int w = t >> 5, l = t & 31;
    __shared__ float smx[4], ssm[4];

    float4 va = ((const float4*)p)[t * 2];
    float4 vb = ((const float4*)p)[t * 2 + 1];
    float v[8] = {va.x, va.y, va.z, va.w, vb.x, vb.y, vb.z, vb.w};

    float mx = v[0];
#pragma unroll
    for (int i = 1; i < 8; i++) mx = fmaxf(mx, v[i]);
#pragma unroll
    for (int o = 16; o; o >>= 1) mx = fmaxf(mx, __shfl_xor_sync(0xffffffffu, mx, o));
    if (l == 0) smx[w] = mx;
    __syncthreads();
    mx = fmaxf(fmaxf(smx[0], smx[1]), fmaxf(smx[2], smx[3]));

    float s = 0.f;
#pragma unroll
    for (int i = 0; i < 8; i++) {
        v[i] = __expf(v[i] - mx);
        s += v[i];
    }
#pragma unroll
    for (int o = 16; o; o >>= 1) s += __shfl_xor_sync(0xffffffffu, s, o);
    if (l == 0) ssm[w] = s;
    __syncthreads();
    s = ssm[0] + ssm[1] + ssm[2] + ssm[3];
    float inv = 1.f / s;

#pragma unroll
    for (int i = 0; i < 8; i++) v[i] *= inv;
    float4 o0 = make_float4(v[0], v[1], v[2], v[3]);
    float4 o1 = make_float4(v[4], v[5], v[6], v[7]);
    ((float4*)p)[t * 2] = o0;
    ((float4*)p)[t * 2 + 1] = o1;

    __nv_bfloat16 hh[8], ll[8];
#pragma unroll
    for (int i = 0; i < 8; i++) f2hl(v[i], hh[i], ll[i]);
    uint4 uh, ul;
    uh.x = pk2(hh[0], hh[1]); uh.y = pk2(hh[2], hh[3]);
    uh.z = pk2(hh[4], hh[5]); uh.w = pk2(hh[6], hh[7]);
    ul.x = pk2(ll[0], ll[1]); ul.y = pk2(ll[2], ll[3]);
    ul.z = pk2(ll[4], ll[5]); ul.w = pk2(ll[6], ll[7]);
    ((uint4*)(ah + rowi * SEQ))[t] = uh;
    ((uint4*)(al + rowi * SEQ))[t] = ul;
}

// ======================= host ====================================================
extern "C" void kernel_launch(void* const* d_in, const int* in_sizes, int n_in,
                              void* d_out, int out_size)
{
    const float* v_in  = (const float*)d_in[0];
    const float* key   = (const float*)d_in[1];
    const float* query = (const float*)d_in[2];
    const void*  mask  = d_in[3];
    const float* Wq = (const float*)d_in[4];
    const float* bq = (const float*)d_in[5];
    const float* Wk = (const float*)d_in[6];
    const float* bk = (const float*)d_in[7];
    const float* Wv = (const float*)d_in[8];
    const float* bv = (const float*)d_in[9];
    const float* Wm = (const float*)d_in[10];
    const float* bm = (const float*)d_in[11];
    float* out = (float*)d_out;

    const long long ATTED_N = (long long)BQ * SEQ * NHID;
    const long long ATT_N   = (long long)BQ * HEADS * SEQ * SEQ;

#define GETP(sym, ty, var) ty* var; cudaGetSymbolAddress((void**)&var, sym)
    GETP(g_in3h, __nv_bfloat16, in3h); GETP(g_in3l, __nv_bfloat16, in3l);
    GETP(g_w4h, __nv_bfloat16, w4h); GETP(g_w4l, __nv_bfloat16, w4l);
    GETP(g_qkvh, __nv_bfloat16, qkvh); GETP(g_qkvl, __nv_bfloat16, qkvl);
    GETP(g_vth, __nv_bfloat16, vth); GETP(g_vtl, __nv_bfloat16, vtl);
    GETP(g_aedh, __nv_bfloat16, aedh); GETP(g_aedl, __nv_bfloat16, aedl);
    GETP(g_atth, __nv_bfloat16, atth); GETP(g_attl, __nv_bfloat16, attl);
    GETP(g_bias3, float, bias3);
    GETP(g_attf, float, attf);
    GETP(g_mask, unsigned char, maskp);
#undef GETP

    __nv_bfloat16* qh = qkvh;               __nv_bfloat16* ql = qkvl;
    __nv_bfloat16* kh = qkvh + O_N;         __nv_bfloat16* kl = qkvl + O_N;
    __nv_bfloat16* vh = qkvh + 2 * O_N;     __nv_bfloat16* vl = qkvl + 2 * O_N;

    float* att_ptr;
    float* atted_ptr = out;
    if ((long long)out_size >= ATTED_N + ATT_N) {
        att_ptr = out + ATTED_N;
    } else {
        att_ptr = attf;
    }

    cudaFuncSetAttribute(gemm3<0>, cudaFuncAttributeMaxDynamicSharedMemorySize, GEMM_SMEM);
    cudaFuncSetAttribute(gemm3<1>, cudaFuncAttributeMaxDynamicSharedMemorySize, GEMM_SMEM);
    cudaFuncSetAttribute(gemm3<2>, cudaFuncAttributeMaxDynamicSharedMemorySize, GEMM_SMEM);

    const float scale = 1.0f / sqrtf((float)DKH);
    dim3 blk(128);

    // (0) input conversions (fused q/k/v)
    {
        int n4 = (int)(IN_N / 4);
        dim3 g((n4 + 255) / 256, 3);
        conv_all<<<g, 256>>>(query, key, v_in, in3h, in3l, n4);
    }
    // (1) weight transposes (fused)
    {
        dim3 g(32, 32, 4), b(32, 8);
        transW_all<<<g, b>>>(Wq, Wk, Wv, Wm, w4h, w4l);
    }
    // (2) bias gather
    gather_bias<<<(NHID + 255) / 256, 256>>>(bq, bk, bv, bias3);

    // (3) ALL THREE projections in ONE launch
    {
        dim3 grid(NHID / 64, (BQ * SEQ) / 128, 3);
        gemm3<0><<<grid, blk, GEMM_SMEM>>>(in3h, in3l, RDIM, 0, (long long)IN_N,
                                           w4h, w4l, RDIM, 0, (long long)W_N,
                                           bias3, (long long)NHID,
                                           nullptr, qkvh, qkvl, NHID, 0, (long long)O_N,
                                           RDIM, nullptr, 0.f);
    }

    // (4) V transpose per batch
    {
        dim3 g(32, 32, BQ), b(32, 8);
        transV<<<g, b>>>(vh, vl, vth, vtl);
    }

    // (5,6) mask canonicalization
    detect_mask_mode<<<1, 256>>>((const unsigned int*)mask);
    convert_mask<<<(BQ * SEQ + 255) / 256, 256>>>(mask, maskp, BQ * SEQ);

    // (7) Scores
    {
        dim3 grid(SEQ / 64, SEQ / 128, BQ * HEADS);
        gemm3<2><<<grid, blk, GEMM_SMEM>>>(qh, ql, NHID, (long long)SEQ * NHID, (long long)DKH,
                                           kh, kl, NHID, (long long)SEQ * NHID, (long long)DKH,
                                           nullptr, 0,
                                           att_ptr, nullptr, nullptr, SEQ,
                                           (long long)HEADS * SEQ * SEQ, (long long)SEQ * SEQ,
                                           DKH, maskp, scale);
    }

    // (8) Softmax in place (f32) + hi/lo bf16 copies for PV
    softmax_rows<<<(unsigned)(BQ * HEADS * SEQ), dim3(128)>>>(att_ptr, atth, attl);

    // (9) PV: atted = att @ V^T -> hi/lo bf16
    {
        dim3 grid(DKH / 64, SEQ / 128, BQ * HEADS);
        gemm3<0><<<grid, blk, GEMM_SMEM>>>(atth, attl, SEQ,
                                           (long long)HEADS * SEQ * SEQ, (long long)SEQ * SEQ,
                                           vth, vtl, SEQ,
                                           (long long)SEQ * NHID, (long long)DKH * SEQ,
                                           nullptr, 0,
                                           nullptr, aedh, aedl, NHID,
                                           (long long)SEQ * NHID, (long long)DKH,
                                           SEQ, nullptr, 0.f);
    }

    // (10) Output projection (weight slice 3 = Wm)
    {
        dim3 grid(NHID / 64, (BQ * SEQ) / 128, 1);
        gemm3<1><<<grid, blk, GEMM_SMEM>>>(aedh, aedl, NHID, 0, 0,
                                           w4h + 3 * W_N, w4l + 3 * W_N, NHID, 0, 0,
                                           bm, 0,
                                           atted_ptr, nullptr, nullptr, NHID, 0, 0,
                                           NHID, nullptr, 0.f);
    }
}